// round 10
// baseline (speedup 1.0000x reference)
#include <cuda_runtime.h>
#include <cuda_fp8.h>
#include <cstdint>
#include <cstring>

// ---------------- problem constants ----------------
#define M_CANDS 131072
#define N_ROWS  2048
#define DIM     64
#define KSEL    11                 // k+1 smallest; smallest (self) dropped later

// ---------------- tiling ----------------
#define PARTS    16                      // candidate partitions (screen lists)
#define ROWS_CTA 32                      // x rows per CTA (2 warps x 16 rows)
#define ROWTILES (N_ROWS / ROWS_CTA)     // 64
#define CPART    (M_CANDS / PARTS)       // 8192 candidates per CTA
#define TN       256                     // candidates per smem tile
#define NT       (CPART / TN)            // 32 tiles
#define THREADS  64
#define TILE_BYTES (TN * 64)             // 16384 (fp8: 64B per candidate)
#define BN_BYTES   (TN * 4)              // 1024

// ---------------- smem layout (bytes) ----------------
#define SM_MBAR  0                       // 3 mbarriers
#define SM_B     1024
#define SM_BN    (SM_B + 3 * TILE_BYTES)          // 50176
#define SMEM_TOTAL (SM_BN + 3 * BN_BYTES)         // 53248

#define POS_INF __int_as_float(0x7f800000)
#define NEG_INF __int_as_float(0xff800000)

// ---------------- device globals (allocation-free scratch) ----------------
// g_b8: e4m3(-2*buf), per-tile FRAGMENT-READY layout:
//   tile t (256 cands), byte off = p*1024 + nb*512 + lane*16 + kc*8 + j*4
//   holds cand c = t*256 + p*16 + nb*8 + (lane>>2),
//   k-bytes kc*32 + j*16 + (lane&3)*4 .. +3
__device__ __align__(128) uint8_t g_b8[(size_t)M_CANDS * DIM];
__device__ __align__(16)  uint8_t g_x8[(size_t)N_ROWS * DIM];   // e4m3(x), row-major
__device__ __align__(16)  float g_bnorm[M_CANDS];               // exact fp32 |b|^2
__device__ __align__(16)  float g_partial[(size_t)N_ROWS * PARTS * KSEL];  // screen keys

// ---------------- helpers ----------------
__device__ __forceinline__ uint32_t smem_u32(const void* p) {
    return (uint32_t)__cvta_generic_to_shared(p);
}

#define MBARRIER_INIT(mbar, cnt) \
    asm volatile("mbarrier.init.shared.b64 [%0], %1;" \
                 :: "r"((uint32_t)(mbar)), "r"((uint32_t)(cnt)) : "memory")
#define MBARRIER_EXPECT_TX(mbar, bytes) \
    asm volatile("mbarrier.arrive.expect_tx.shared.b64 _, [%0], %1;" \
                 :: "r"((uint32_t)(mbar)), "r"((uint32_t)(bytes)) : "memory")
#define MBARRIER_WAIT_PARITY(mbar, parity) do {                                   \
    uint32_t _m = (uint32_t)(mbar); uint32_t _p = (uint32_t)(parity);             \
    asm volatile("{\n\t.reg .pred P1;\n\t"                                        \
        "WAIT_LOOP_%=:\n\t"                                                       \
        "mbarrier.try_wait.parity.acquire.cta.shared::cta.b64 P1, [%0], %1, 0x989680;\n\t" \
        "@P1 bra.uni WAIT_DONE_%=;\n\t"                                           \
        "bra.uni WAIT_LOOP_%=;\n\t"                                               \
        "WAIT_DONE_%=:\n\t}" :: "r"(_m), "r"(_p) : "memory");                     \
} while (0)

__device__ __forceinline__ void bulk_g2s(uint32_t dst, const void* src,
                                         uint32_t bytes, uint32_t mbar) {
    asm volatile(
        "cp.async.bulk.shared::cluster.global.mbarrier::complete_tx::bytes "
        "[%0], [%1], %2, [%3];"
        :: "r"(dst), "l"(__cvta_generic_to_global(src)), "r"(bytes), "r"(mbar)
        : "memory");
}

// m16n8k32 row.col e4m3 -> f32, D += A*B (D aliases C)
__device__ __forceinline__ void mma16832(float c[4], const uint32_t a[4],
                                         uint32_t b0, uint32_t b1) {
    asm volatile(
        "mma.sync.aligned.m16n8k32.row.col.f32.e4m3.e4m3.f32 "
        "{%0,%1,%2,%3}, {%4,%5,%6,%7}, {%8,%9}, {%0,%1,%2,%3};"
        : "+f"(c[0]), "+f"(c[1]), "+f"(c[2]), "+f"(c[3])
        : "r"(a[0]), "r"(a[1]), "r"(a[2]), "r"(a[3]), "r"(b0), "r"(b1));
}

// register-resident ascending insert; v > h[10] is a no-op
__device__ __forceinline__ void bubble_insert(float* h, float v) {
#pragma unroll
    for (int j = 0; j < KSEL; ++j) {
        float lo = fminf(h[j], v);
        v = fmaxf(h[j], v);
        h[j] = lo;
    }
}

// merge my ascending 11-list with lane^mask's; keep 11 smallest, ascending
__device__ __forceinline__ void merge11(float h[KSEL], int mask) {
    float b[KSEL];
#pragma unroll
    for (int j = 0; j < KSEL; ++j) b[j] = __shfl_xor_sync(0xffffffffu, h[j], mask);
    float c[16];
#pragma unroll
    for (int i = 0; i < 5; ++i) c[i] = NEG_INF;
#pragma unroll
    for (int i = 0; i < KSEL; ++i) c[5 + i] = fminf(h[i], b[10 - i]);
#pragma unroll
    for (int d = 8; d >= 1; d >>= 1)
#pragma unroll
        for (int i = 0; i < 16; ++i)
            if ((i & d) == 0) {
                float lo = fminf(c[i], c[i | d]);
                float hi = fmaxf(c[i], c[i | d]);
                c[i] = lo; c[i | d] = hi;
            }
#pragma unroll
    for (int i = 0; i < KSEL; ++i) h[i] = c[5 + i];
}

// sortable screen key: clamp d2 >= 0, replace low 13 mantissa bits with idx
__device__ __forceinline__ float mk_key(float d2, int idx) {
    uint32_t b = __float_as_uint(fmaxf(d2, 0.f));
    return __uint_as_float((b & 0xFFFFE000u) | (uint32_t)idx);
}

__device__ __forceinline__ uint32_t fp8x4(float a, float b, float c, float d) {
    __nv_fp8x4_e4m3 v(make_float4(a, b, c, d));
    uint32_t w;
    memcpy(&w, &v, 4);
    return w;
}

// ---------------- prep kernels ----------------
// quantize -2*buf to e4m3 and write the fragment-ready tile layout with
// fully coalesced STG.128 (permutation goes through smem).
__global__ void prep_b8_kernel(const float* __restrict__ buf) {
    __shared__ uint32_t sw[TN * 16];         // 16 KB: cand-major words
    const int tid = threadIdx.x;
    const int c   = blockIdx.x * TN + tid;   // one tile per block

    const float4* s = reinterpret_cast<const float4*>(buf) + (size_t)c * 16;
    float n = 0.f;
    uint32_t w[16];
#pragma unroll
    for (int q = 0; q < 16; ++q) {
        float4 v = s[q];
        n = fmaf(v.x, v.x, n); n = fmaf(v.y, v.y, n);
        n = fmaf(v.z, v.z, n); n = fmaf(v.w, v.w, n);
        w[q] = fp8x4(-2.f * v.x, -2.f * v.y, -2.f * v.z, -2.f * v.w);
    }
#pragma unroll
    for (int q = 0; q < 16; ++q) sw[tid * 16 + q] = w[q];
    g_bnorm[c] = n;
    __syncthreads();

    uint4* dst = reinterpret_cast<uint4*>(g_b8 + (size_t)blockIdx.x * TILE_BYTES);
#pragma unroll
    for (int i = 0; i < 4; ++i) {
        int idx  = tid + i * TN;             // 0..1023 = (p*2+nb)*32 + lane
        int lane = idx & 31;
        int pn   = idx >> 5;                 // p*2 + nb
        int cc   = pn * 8 + (lane >> 2);
        int tig  = lane & 3;
        uint4 o;
        o.x = sw[cc * 16 + tig];
        o.y = sw[cc * 16 + tig + 4];
        o.z = sw[cc * 16 + tig + 8];
        o.w = sw[cc * 16 + tig + 12];
        dst[idx] = o;                        // coalesced
    }
}

__global__ void prep_x8_kernel(const float* __restrict__ x) {
    int c = blockIdx.x * 256 + threadIdx.x;
    const float4* s = reinterpret_cast<const float4*>(x) + (size_t)c * 16;
    uint32_t* dst = reinterpret_cast<uint32_t*>(g_x8 + (size_t)c * 64);
#pragma unroll
    for (int q = 0; q < 16; ++q) {
        float4 v = s[q];
        dst[q] = fp8x4(v.x, v.y, v.z, v.w);
    }
}

// ---------------- main fused fp8-GEMM + top-k screen kernel ----------------
extern __shared__ char smem[];

__global__ void __launch_bounds__(THREADS, 4)
pbe_mma8_kernel() {
    const int tid  = threadIdx.x;
    const int lane = tid & 31;
    const int w    = tid >> 5;           // 0..1
    const int g    = lane >> 2;          // 0..7
    const int tig  = lane & 3;           // 0..3
    const int part = blockIdx.x;         // 0..15
    const int rt   = blockIdx.y;         // 0..63
    const int cand_base = part * CPART;
    const int row_base  = rt * ROWS_CTA + w * 16;

    const uint32_t sbase = smem_u32(smem);
    const uint32_t mb0   = sbase + SM_MBAR;

    // ---- A fragments: rows (row_base+g, +8), e4m3, K=64 as 2 k-chunks ----
    uint32_t afr[2][4];
    {
        const uint8_t* xr0 = g_x8 + (size_t)(row_base + g) * 64;
        const uint8_t* xr1 = g_x8 + (size_t)(row_base + g + 8) * 64;
#pragma unroll
        for (int kc = 0; kc < 2; ++kc) {
            afr[kc][0] = *reinterpret_cast<const uint32_t*>(xr0 + kc * 32 + tig * 4);
            afr[kc][1] = *reinterpret_cast<const uint32_t*>(xr1 + kc * 32 + tig * 4);
            afr[kc][2] = *reinterpret_cast<const uint32_t*>(xr0 + kc * 32 + tig * 4 + 16);
            afr[kc][3] = *reinterpret_cast<const uint32_t*>(xr1 + kc * 32 + tig * 4 + 16);
        }
    }

    // ---- mbarriers + prologue staging ----
    if (tid == 0) {
        MBARRIER_INIT(mb0 + 0,  1);
        MBARRIER_INIT(mb0 + 8,  1);
        MBARRIER_INIT(mb0 + 16, 1);
    }
    __syncthreads();

    auto issue = [&](int t) {            // thread 0 only
        int s = t % 3;
        uint32_t bar = mb0 + s * 8;
        MBARRIER_EXPECT_TX(bar, TILE_BYTES + BN_BYTES);
        bulk_g2s(sbase + SM_B + s * TILE_BYTES,
                 g_b8 + (size_t)(cand_base + t * TN) * 64, TILE_BYTES, bar);
        bulk_g2s(sbase + SM_BN + s * BN_BYTES,
                 g_bnorm + cand_base + t * TN, BN_BYTES, bar);
    };
    if (tid == 0) { issue(0); issue(1); }

    // ---- top-11 screen-key lists for this thread's 2 rows ----
    float h0[KSEL], h1[KSEL];
#pragma unroll
    for (int j = 0; j < KSEL; ++j) { h0[j] = POS_INF; h1[j] = POS_INF; }

    uint32_t ph[3] = {0, 0, 0};
    const uint32_t fbase = (uint32_t)(lane * 16);

    for (int t = 0; t < NT; ++t) {
        const int slot = t % 3;
        __syncthreads();                 // all warps finished compute(t-1)
        if (t + 2 < NT && tid == 0) issue(t + 2);
        MBARRIER_WAIT_PARITY(mb0 + slot * 8, ph[slot]);
        ph[slot] ^= 1;

        const char*  btile = smem + SM_B + slot * TILE_BYTES;
        const float* bns   = reinterpret_cast<const float*>(
                                 smem + SM_BN + slot * BN_BYTES) + tig * 2;
        const int ib = t * TN + tig * 2;     // in-partition idx base (13 bits)

        // fragment pair for p: f[nb] = {kc0b0, kc0b1, kc1b0, kc1b1}
        uint4 fA[2], fB[2];
        auto load_pair = [&](int p, uint4 f[2]) {
            f[0] = *reinterpret_cast<const uint4*>(btile + p * 1024 + fbase);
            f[1] = *reinterpret_cast<const uint4*>(btile + p * 1024 + 512 + fbase);
        };
        load_pair(0, fA);

#pragma unroll
        for (int p = 0; p < 16; ++p) {
            uint4* fc = (p & 1) ? fB : fA;
            uint4* fn = (p & 1) ? fA : fB;
            if (p < 15) load_pair(p + 1, fn);

            float acc[2][4];
#pragma unroll
            for (int q = 0; q < 2; ++q) {
                const float2 bnv = *reinterpret_cast<const float2*>(
                    &bns[(p * 2 + q) * 8]);
                acc[q][0] = bnv.x; acc[q][1] = bnv.y;
                acc[q][2] = bnv.x; acc[q][3] = bnv.y;
            }
            mma16832(acc[0], afr[0], fc[0].x, fc[0].y);
            mma16832(acc[0], afr[1], fc[0].z, fc[0].w);
            mma16832(acc[1], afr[0], fc[1].x, fc[1].y);
            mma16832(acc[1], afr[1], fc[1].z, fc[1].w);

            // acc ~= bn - 2*dot (fp8 screen); pack idx into low mantissa bits
#pragma unroll
            for (int q = 0; q < 2; ++q) {
                const int cb = ib + (p * 2 + q) * 8;
                if (fminf(acc[q][0], acc[q][1]) < h0[KSEL - 1]) {
                    if (acc[q][0] < h0[KSEL - 1]) bubble_insert(h0, mk_key(acc[q][0], cb));
                    if (acc[q][1] < h0[KSEL - 1]) bubble_insert(h0, mk_key(acc[q][1], cb + 1));
                }
                if (fminf(acc[q][2], acc[q][3]) < h1[KSEL - 1]) {
                    if (acc[q][2] < h1[KSEL - 1]) bubble_insert(h1, mk_key(acc[q][2], cb));
                    if (acc[q][3] < h1[KSEL - 1]) bubble_insert(h1, mk_key(acc[q][3], cb + 1));
                }
            }
        }
    }

    // ---- merge keys across the 4 tig lanes; tig 0 writes per (row,part) ----
    merge11(h0, 1); merge11(h0, 2);
    merge11(h1, 1); merge11(h1, 2);
    if (tig == 0) {
        float* p0 = &g_partial[((size_t)(row_base + g)     * PARTS + part) * KSEL];
        float* p1 = &g_partial[((size_t)(row_base + g + 8) * PARTS + part) * KSEL];
#pragma unroll
        for (int j = 0; j < KSEL; ++j) { p0[j] = h0[j]; p1[j] = h1[j]; }
    }
}

// ---------------- final: exact fp32 rescore; one block (2 warps) per row ----
__global__ void final_kernel(const float* __restrict__ x,
                             const float* __restrict__ buf,
                             float* __restrict__ out) {
    __shared__ __align__(16) float xs[64];
    __shared__ float hb[KSEL];
    const int tid  = threadIdx.x;
    const int lane = tid & 31;
    const int w    = tid >> 5;           // warp 0: parts 0-7, warp 1: parts 8-15
    const int row  = blockIdx.x;

    xs[tid] = x[(size_t)row * DIM + tid];
    __syncthreads();
    const float4* xr = reinterpret_cast<const float4*>(xs);
    const float* pk = &g_partial[((size_t)row * PARTS + w * 8) * KSEL];  // 88 keys

    float L0 = POS_INF, L1 = POS_INF, L2v = POS_INF;   // per-lane top-3 (<=3 keys)
    for (int i = lane; i < 8 * KSEL; i += 32) {
        uint32_t bits = __float_as_uint(pk[i]);
        int part = w * 8 + i / KSEL;
        size_t gi = (size_t)part * CPART + (bits & 8191u);
        const float4* br = reinterpret_cast<const float4*>(buf + gi * DIM);
        float d2 = 0.f;
#pragma unroll
        for (int q = 0; q < 16; ++q) {
            float4 b4 = br[q], x4 = xr[q];
            float dx = x4.x - b4.x; d2 = fmaf(dx, dx, d2);
            dx = x4.y - b4.y; d2 = fmaf(dx, dx, d2);
            dx = x4.z - b4.z; d2 = fmaf(dx, dx, d2);
            dx = x4.w - b4.w; d2 = fmaf(dx, dx, d2);
        }
        if (d2 < L2v) {
            if (d2 < L1) { L2v = L1; if (d2 < L0) { L1 = L0; L0 = d2; } else L1 = d2; }
            else L2v = d2;
        }
    }

    float h[KSEL];
    h[0] = L0; h[1] = L1; h[2] = L2v;
#pragma unroll
    for (int j = 3; j < KSEL; ++j) h[j] = POS_INF;
    merge11(h, 1); merge11(h, 2); merge11(h, 4); merge11(h, 8); merge11(h, 16);

    if (w == 1 && lane == 0) {
#pragma unroll
        for (int j = 0; j < KSEL; ++j) hb[j] = h[j];
    }
    __syncthreads();
    if (tid == 0) {
#pragma unroll
        for (int j = 0; j < KSEL; ++j) bubble_insert(h, hb[j]);
        float s = 0.f;
#pragma unroll
        for (int j = 1; j < KSEL; ++j)          // drop self-match (h[0] == 0)
            s += sqrtf(h[j]);
        out[row] = log1pf(s * (1.f / (KSEL - 1)));
    }
}

// ---------------- launch ----------------
extern "C" void kernel_launch(void* const* d_in, const int* in_sizes, int n_in,
                              void* d_out, int out_size) {
    const float* a = (const float*)d_in[0];
    const float* b = (const float*)d_in[1];
    const float* x = a;
    const float* buf = b;
    if (in_sizes[0] > in_sizes[1]) { x = b; buf = a; }

    cudaFuncSetAttribute(pbe_mma8_kernel,
                         cudaFuncAttributeMaxDynamicSharedMemorySize, SMEM_TOTAL);

    prep_b8_kernel<<<M_CANDS / TN, TN>>>(buf);
    prep_x8_kernel<<<N_ROWS / 256, 256>>>(x);

    dim3 grid(PARTS, ROWTILES);   // 16 x 64 = 1024 CTAs, ~7 per SM
    pbe_mma8_kernel<<<grid, THREADS, SMEM_TOTAL>>>();

    final_kernel<<<N_ROWS, 64>>>(x, buf, (float*)d_out);
}

// round 11
// speedup vs baseline: 1.2633x; 1.2633x over previous
#include <cuda_runtime.h>
#include <cuda_bf16.h>
#include <cstdint>

// ---------------- problem constants ----------------
#define M_CANDS 131072
#define N_ROWS  2048
#define DIM     64
#define KSEL    11                 // k+1 smallest; smallest (self) dropped later

// ---------------- tiling / work decomposition ----------------
#define PARTS    16                      // candidate partitions
#define NCHUNK   8                       // tile-chunks per partition
#define CH_TILES 4                       // tiles per chunk (32 total per part)
#define ROWS_CTA 256                     // x rows per unit (16 warps x 16 rows)
#define ROWTILES (N_ROWS / ROWS_CTA)     // 8
#define CPART    (M_CANDS / PARTS)       // 8192
#define TN       256                     // candidates per smem tile
#define THREADS  512
#define NUNITS   (ROWTILES * PARTS * NCHUNK)   // 1024
#define NLISTS   (PARTS * NCHUNK)              // 128 lists per row
#define GRID_MAIN 152
#define TILE_BYTES (TN * 128)            // 32768
#define BN_BYTES   (TN * 4)              // 1024

// ---------------- smem layout (bytes) ----------------
#define SM_MBAR  0                       // 3 mbarriers
#define SM_B     1024
#define SM_BN    (SM_B + 3 * TILE_BYTES)          // 99328
#define SMEM_TOTAL (SM_BN + 3 * BN_BYTES)         // 102400

#define POS_INF __int_as_float(0x7f800000)
#define NEG_INF __int_as_float(0xff800000)

// ---------------- device globals (allocation-free scratch) ----------------
__device__ __align__(128) __nv_bfloat16 g_bbf[(size_t)M_CANDS * DIM]; // -2*buf, bf16, tile-swizzled
__device__ __align__(16)  __nv_bfloat16 g_xbf[(size_t)N_ROWS * DIM];
__device__ __align__(16)  float g_bnorm[M_CANDS];
__device__ __align__(16)  float g_xnorm[N_ROWS];
__device__ __align__(16)  float g_partial[(size_t)N_ROWS * NLISTS * KSEL];
__device__ int g_unit;                   // dynamic work counter (reset each launch)

// ---------------- helpers ----------------
__device__ __forceinline__ uint32_t smem_u32(const void* p) {
    return (uint32_t)__cvta_generic_to_shared(p);
}
#define SWZ128(off) ((off) ^ (((off) >> 3) & 0x70))

#define MBARRIER_INIT(mbar, cnt) \
    asm volatile("mbarrier.init.shared.b64 [%0], %1;" \
                 :: "r"((uint32_t)(mbar)), "r"((uint32_t)(cnt)) : "memory")
#define MBARRIER_EXPECT_TX(mbar, bytes) \
    asm volatile("mbarrier.arrive.expect_tx.shared.b64 _, [%0], %1;" \
                 :: "r"((uint32_t)(mbar)), "r"((uint32_t)(bytes)) : "memory")
#define MBARRIER_WAIT_PARITY(mbar, parity) do {                                   \
    uint32_t _m = (uint32_t)(mbar); uint32_t _p = (uint32_t)(parity);             \
    asm volatile("{\n\t.reg .pred P1;\n\t"                                        \
        "WAIT_LOOP_%=:\n\t"                                                       \
        "mbarrier.try_wait.parity.acquire.cta.shared::cta.b64 P1, [%0], %1, 0x989680;\n\t" \
        "@P1 bra.uni WAIT_DONE_%=;\n\t"                                           \
        "bra.uni WAIT_LOOP_%=;\n\t"                                               \
        "WAIT_DONE_%=:\n\t}" :: "r"(_m), "r"(_p) : "memory");                     \
} while (0)

__device__ __forceinline__ void bulk_g2s(uint32_t dst, const void* src,
                                         uint32_t bytes, uint32_t mbar) {
    asm volatile(
        "cp.async.bulk.shared::cluster.global.mbarrier::complete_tx::bytes "
        "[%0], [%1], %2, [%3];"
        :: "r"(dst), "l"(__cvta_generic_to_global(src)), "r"(bytes), "r"(mbar)
        : "memory");
}

// ldmatrix x4: 4 8x8 b16 matrices; lane supplies one 16B row address
__device__ __forceinline__ void ldsm4(uint32_t* r, uint32_t addr) {
    asm volatile("ldmatrix.sync.aligned.m8n8.x4.shared.b16 {%0,%1,%2,%3}, [%4];"
                 : "=r"(r[0]), "=r"(r[1]), "=r"(r[2]), "=r"(r[3]) : "r"(addr));
}

// m16n8k16 row.col bf16 -> f32, D += A*B (D aliases C)
__device__ __forceinline__ void mma16816(float c[4], const uint32_t a[4],
                                         uint32_t b0, uint32_t b1) {
    asm volatile(
        "mma.sync.aligned.m16n8k16.row.col.f32.bf16.bf16.f32 "
        "{%0,%1,%2,%3}, {%4,%5,%6,%7}, {%8,%9}, {%0,%1,%2,%3};"
        : "+f"(c[0]), "+f"(c[1]), "+f"(c[2]), "+f"(c[3])
        : "r"(a[0]), "r"(a[1]), "r"(a[2]), "r"(a[3]), "r"(b0), "r"(b1));
}

// register-resident ascending insert; v > h[10] is a no-op
__device__ __forceinline__ void bubble_insert(float* h, float v) {
#pragma unroll
    for (int j = 0; j < KSEL; ++j) {
        float lo = fminf(h[j], v);
        v = fmaxf(h[j], v);
        h[j] = lo;
    }
}

// merge my ascending 11-list with lane^mask's; keep 11 smallest, ascending
__device__ __forceinline__ void merge11(float h[KSEL], int mask) {
    float b[KSEL];
#pragma unroll
    for (int j = 0; j < KSEL; ++j) b[j] = __shfl_xor_sync(0xffffffffu, h[j], mask);
    float c[16];
#pragma unroll
    for (int i = 0; i < 5; ++i) c[i] = NEG_INF;
#pragma unroll
    for (int i = 0; i < KSEL; ++i) c[5 + i] = fminf(h[i], b[10 - i]);
#pragma unroll
    for (int d = 8; d >= 1; d >>= 1)
#pragma unroll
        for (int i = 0; i < 16; ++i)
            if ((i & d) == 0) {
                float lo = fminf(c[i], c[i | d]);
                float hi = fmaxf(c[i], c[i | d]);
                c[i] = lo; c[i | d] = hi;
            }
#pragma unroll
    for (int i = 0; i < KSEL; ++i) h[i] = c[5 + i];
}

// ---------------- prep kernels ----------------
__global__ void prep_buf_kernel(const float* __restrict__ buf) {
    int c = blockIdx.x * 256 + threadIdx.x;
    const float4* s = reinterpret_cast<const float4*>(buf) + (size_t)c * 16;
    uint4 pk[8];
    uint32_t* pw = reinterpret_cast<uint32_t*>(pk);
    float n = 0.f;
#pragma unroll
    for (int q = 0; q < 16; ++q) {
        float4 v = s[q];
        n = fmaf(v.x, v.x, n); n = fmaf(v.y, v.y, n);
        n = fmaf(v.z, v.z, n); n = fmaf(v.w, v.w, n);
        __nv_bfloat162 a = __floats2bfloat162_rn(-2.f * v.x, -2.f * v.y);
        __nv_bfloat162 b = __floats2bfloat162_rn(-2.f * v.z, -2.f * v.w);
        pw[2 * q]     = reinterpret_cast<uint32_t&>(a);
        pw[2 * q + 1] = reinterpret_cast<uint32_t&>(b);
    }
    char* blk = reinterpret_cast<char*>(g_bbf) + (size_t)(c >> 8) * TILE_BYTES;
    uint32_t r = (uint32_t)(c & 255);
#pragma unroll
    for (int q = 0; q < 8; ++q)
        *reinterpret_cast<uint4*>(blk + SWZ128(r * 128 + q * 16)) = pk[q];
    g_bnorm[c] = n;
}

__global__ void prep_x_kernel(const float* __restrict__ x) {
    if (blockIdx.x == 0 && threadIdx.x == 0) g_unit = 0;   // reset work counter
    int c = blockIdx.x * 256 + threadIdx.x;
    const float4* s = reinterpret_cast<const float4*>(x) + (size_t)c * 16;
    uint4 pk[8];
    uint32_t* pw = reinterpret_cast<uint32_t*>(pk);
    float n = 0.f;
#pragma unroll
    for (int q = 0; q < 16; ++q) {
        float4 v = s[q];
        n = fmaf(v.x, v.x, n); n = fmaf(v.y, v.y, n);
        n = fmaf(v.z, v.z, n); n = fmaf(v.w, v.w, n);
        __nv_bfloat162 a = __floats2bfloat162_rn(v.x, v.y);
        __nv_bfloat162 b = __floats2bfloat162_rn(v.z, v.w);
        pw[2 * q]     = reinterpret_cast<uint32_t&>(a);
        pw[2 * q + 1] = reinterpret_cast<uint32_t&>(b);
    }
    uint4* dst = reinterpret_cast<uint4*>(g_xbf) + (size_t)c * 8;
#pragma unroll
    for (int i = 0; i < 8; ++i) dst[i] = pk[i];
    g_xnorm[c] = n;
}

// ---------------- persistent fused GEMM + top-k kernel ----------------
extern __shared__ char smem[];

__global__ void __launch_bounds__(THREADS, 1)
pbe_persist_kernel() {
    __shared__ int s_u;
    const int tid  = threadIdx.x;
    const int lane = tid & 31;
    const int w    = tid >> 5;           // 0..15
    const int g    = lane >> 2;          // 0..7
    const int tig  = lane & 3;           // 0..3

    const uint32_t sbase = smem_u32(smem);
    const uint32_t mb0   = sbase + SM_MBAR;

    // per-lane ldmatrix offsets (swizzle XOR applied last, no carries)
    const uint32_t l8  = (uint32_t)(lane & 7);
    const uint32_t qof = (uint32_t)((lane >> 3) * 16);
    const uint32_t sw  = l8 << 4;
    const uint32_t lm_off0 = l8 * 128 + (qof ^ sw);          // k bytes 0..63
    const uint32_t lm_off1 = l8 * 128 + ((qof + 64) ^ sw);   // k bytes 64..127

    if (tid == 0) {
        MBARRIER_INIT(mb0 + 0,  1);
        MBARRIER_INIT(mb0 + 8,  1);
        MBARRIER_INIT(mb0 + 16, 1);
    }

    uint32_t ph[3] = {0, 0, 0};
    int tc = 0;                          // running tile counter -> slot cycling

    for (;;) {
        __syncthreads();                 // prev unit fully computed; s_u reusable
        if (tid == 0) s_u = atomicAdd(&g_unit, 1);
        __syncthreads();
        const int u = s_u;
        if (u >= NUNITS) break;

        const int rowtile = u >> 7;              // 0..7
        const int part    = (u >> 3) & 15;       // 0..15
        const int chunk   = u & 7;               // 0..7
        const int row_base = rowtile * ROWS_CTA + w * 16;
        const size_t cb0 = (size_t)(part * CPART + chunk * CH_TILES * TN);

        // ---- A fragments for this unit's rows ----
        uint32_t afr[4][4];
        {
            const uint32_t* x0 = reinterpret_cast<const uint32_t*>(
                g_xbf + (size_t)(row_base + g) * DIM);
            const uint32_t* x1 = reinterpret_cast<const uint32_t*>(
                g_xbf + (size_t)(row_base + g + 8) * DIM);
#pragma unroll
            for (int kc = 0; kc < 4; ++kc) {
                afr[kc][0] = x0[kc * 8 + tig];
                afr[kc][1] = x1[kc * 8 + tig];
                afr[kc][2] = x0[kc * 8 + tig + 4];
                afr[kc][3] = x1[kc * 8 + tig + 4];
            }
        }

        auto issue = [&](int t) {        // thread 0 only; slot = (tc+t)%3
            int s = (tc + t) % 3;
            uint32_t bar = mb0 + s * 8;
            MBARRIER_EXPECT_TX(bar, TILE_BYTES + BN_BYTES);
            bulk_g2s(sbase + SM_B + s * TILE_BYTES,
                     reinterpret_cast<const char*>(g_bbf) + (cb0 + t * TN) * 128,
                     TILE_BYTES, bar);
            bulk_g2s(sbase + SM_BN + s * BN_BYTES,
                     g_bnorm + cb0 + t * TN, BN_BYTES, bar);
        };
        if (tid == 0) { issue(0); issue(1); }

        float h0[KSEL], h1[KSEL];
#pragma unroll
        for (int j = 0; j < KSEL; ++j) { h0[j] = POS_INF; h1[j] = POS_INF; }

        for (int t = 0; t < CH_TILES; ++t) {
            const int slot = (tc + t) % 3;
            if (t > 0) __syncthreads();  // all warps finished compute(t-1)
            if (t + 2 < CH_TILES && tid == 0) issue(t + 2);
            MBARRIER_WAIT_PARITY(mb0 + slot * 8, ph[slot]);
            ph[slot] ^= 1;

            const uint32_t tb0 = sbase + SM_B + slot * TILE_BYTES + lm_off0;
            const uint32_t tb1 = sbase + SM_B + slot * TILE_BYTES + lm_off1;
            const float*   bns = reinterpret_cast<const float*>(
                                     smem + SM_BN + slot * BN_BYTES) + tig * 2;

            uint32_t fA[2][8], fB[2][8];
            auto load_pair = [&](int p, uint32_t f[2][8]) {
                const uint32_t po = (uint32_t)(p * 2048);
                ldsm4(&f[0][0], tb0 + po);               // nb=2p,   k 0..31
                ldsm4(&f[0][4], tb1 + po);               // nb=2p,   k 32..63
                ldsm4(&f[1][0], tb0 + po + 1024);        // nb=2p+1, k 0..31
                ldsm4(&f[1][4], tb1 + po + 1024);        // nb=2p+1, k 32..63
            };
            load_pair(0, fA);

#pragma unroll
            for (int p = 0; p < 16; ++p) {
                uint32_t (*fc)[8] = (p & 1) ? fB : fA;
                uint32_t (*fn)[8] = (p & 1) ? fA : fB;
                if (p < 15) load_pair(p + 1, fn);

                float acc[2][4];
#pragma unroll
                for (int q = 0; q < 2; ++q) {
                    const float2 bnv = *reinterpret_cast<const float2*>(
                        &bns[(p * 2 + q) * 8]);
                    acc[q][0] = bnv.x; acc[q][1] = bnv.y;
                    acc[q][2] = bnv.x; acc[q][3] = bnv.y;
                }
#pragma unroll
                for (int kc = 0; kc < 4; ++kc) {
                    mma16816(acc[0], afr[kc], fc[0][kc * 2], fc[0][kc * 2 + 1]);
                    mma16816(acc[1], afr[kc], fc[1][kc * 2], fc[1][kc * 2 + 1]);
                }
                // acc IS the distance (bn - 2*dot); |x|^2 deferred
#pragma unroll
                for (int q = 0; q < 2; ++q) {
                    if (fminf(acc[q][0], acc[q][1]) < h0[KSEL - 1]) {
                        if (acc[q][0] < h0[KSEL - 1]) bubble_insert(h0, acc[q][0]);
                        if (acc[q][1] < h0[KSEL - 1]) bubble_insert(h0, acc[q][1]);
                    }
                    if (fminf(acc[q][2], acc[q][3]) < h1[KSEL - 1]) {
                        if (acc[q][2] < h1[KSEL - 1]) bubble_insert(h1, acc[q][2]);
                        if (acc[q][3] < h1[KSEL - 1]) bubble_insert(h1, acc[q][3]);
                    }
                }
            }
        }
        tc += CH_TILES;

        // ---- merge across the 4 tig lanes; tig 0 writes 1 list per row ----
        merge11(h0, 1); merge11(h0, 2);
        merge11(h1, 1); merge11(h1, 2);
        if (tig == 0) {
            const int li = part * NCHUNK + chunk;
            float* p0 = &g_partial[((size_t)(row_base + g)     * NLISTS + li) * KSEL];
            float* p1 = &g_partial[((size_t)(row_base + g + 8) * NLISTS + li) * KSEL];
#pragma unroll
            for (int j = 0; j < KSEL; ++j) { p0[j] = h0[j]; p1[j] = h1[j]; }
        }
    }
}

// ---------------- final merge kernel: 128 threads per row ----------------
__global__ void final_kernel(float* __restrict__ out) {
    __shared__ float wl[4][KSEL];
    const int tid  = threadIdx.x;        // 0..127 <-> list index
    const int lane = tid & 31;
    const int w    = tid >> 5;
    const int row  = blockIdx.x;

    float h[KSEL];
    const float* p = &g_partial[((size_t)row * NLISTS + tid) * KSEL];
#pragma unroll
    for (int j = 0; j < KSEL; ++j) h[j] = p[j];

    merge11(h, 1); merge11(h, 2); merge11(h, 4); merge11(h, 8); merge11(h, 16);
    if (lane == 0) {
#pragma unroll
        for (int j = 0; j < KSEL; ++j) wl[w][j] = h[j];
    }
    __syncthreads();
    if (tid == 0) {
#pragma unroll
        for (int ww = 1; ww < 4; ++ww)
            for (int j = 0; j < KSEL; ++j) {
                float v = wl[ww][j];
                if (v < h[KSEL - 1]) bubble_insert(h, v);
                else break;              // lists are sorted ascending
            }
        float xn = g_xnorm[row];
        float s = 0.f;
#pragma unroll
        for (int j = 1; j < KSEL; ++j)          // drop self-match (h[0])
            s += sqrtf(fmaxf(xn + h[j], 0.f));
        out[row] = log1pf(s * (1.f / (KSEL - 1)));
    }
}

// ---------------- launch ----------------
extern "C" void kernel_launch(void* const* d_in, const int* in_sizes, int n_in,
                              void* d_out, int out_size) {
    const float* a = (const float*)d_in[0];
    const float* b = (const float*)d_in[1];
    const float* x = a;
    const float* buf = b;
    if (in_sizes[0] > in_sizes[1]) { x = b; buf = a; }

    cudaFuncSetAttribute(pbe_persist_kernel,
                         cudaFuncAttributeMaxDynamicSharedMemorySize, SMEM_TOTAL);

    prep_buf_kernel<<<M_CANDS / 256, 256>>>(buf);
    prep_x_kernel<<<N_ROWS / 256, 256>>>(x);        // also resets g_unit

    pbe_persist_kernel<<<GRID_MAIN, THREADS, SMEM_TOTAL>>>();

    final_kernel<<<N_ROWS, 128>>>((float*)d_out);
}

// round 12
// speedup vs baseline: 1.2798x; 1.0131x over previous
#include <cuda_runtime.h>
#include <cuda_bf16.h>
#include <cstdint>

// ---------------- problem constants ----------------
#define M_CANDS 131072
#define N_ROWS  2048
#define DIM     64
#define KSEL    11                 // k+1 smallest; smallest (self) dropped later

// ---------------- tiling / static work decomposition ----------------
#define PARTS    16                      // candidate partitions
#define NCHUNK   8                       // chunks per partition
#define CH_TILES 4                       // tiles per chunk
#define ROWS_CTA 256                     // x rows per unit (16 warps x 16 rows)
#define ROWTILES (N_ROWS / ROWS_CTA)     // 8
#define CPART    (M_CANDS / PARTS)       // 8192
#define TN       256                     // candidates per smem tile
#define THREADS  512
#define NUNITS   (ROWTILES * PARTS * NCHUNK)   // 1024
#define NLISTS   (PARTS * NCHUNK)              // 128 lists per row
#define GRID_MAIN 148
#define TILE_BYTES (TN * 128)            // 32768
#define BN_BYTES   (TN * 4)              // 1024

// ---------------- smem layout (bytes) ----------------
#define SM_MBAR  0                       // 3 mbarriers
#define SM_B     1024
#define SM_BN    (SM_B + 3 * TILE_BYTES)          // 99328
#define SMEM_TOTAL (SM_BN + 3 * BN_BYTES)         // 102400

#define POS_INF __int_as_float(0x7f800000)
#define NEG_INF __int_as_float(0xff800000)

// ---------------- device globals (allocation-free scratch) ----------------
__device__ __align__(128) __nv_bfloat16 g_bbf[(size_t)M_CANDS * DIM]; // -2*buf, bf16, tile-swizzled
__device__ __align__(16)  __nv_bfloat16 g_xbf[(size_t)N_ROWS * DIM];
__device__ __align__(16)  float g_bnorm[M_CANDS];
__device__ __align__(16)  float g_xnorm[N_ROWS];
__device__ __align__(16)  float g_partial[(size_t)N_ROWS * NLISTS * KSEL];

// ---------------- helpers ----------------
__device__ __forceinline__ uint32_t smem_u32(const void* p) {
    return (uint32_t)__cvta_generic_to_shared(p);
}
#define SWZ128(off) ((off) ^ (((off) >> 3) & 0x70))

#define MBARRIER_INIT(mbar, cnt) \
    asm volatile("mbarrier.init.shared.b64 [%0], %1;" \
                 :: "r"((uint32_t)(mbar)), "r"((uint32_t)(cnt)) : "memory")
#define MBARRIER_EXPECT_TX(mbar, bytes) \
    asm volatile("mbarrier.arrive.expect_tx.shared.b64 _, [%0], %1;" \
                 :: "r"((uint32_t)(mbar)), "r"((uint32_t)(bytes)) : "memory")
#define MBARRIER_WAIT_PARITY(mbar, parity) do {                                   \
    uint32_t _m = (uint32_t)(mbar); uint32_t _p = (uint32_t)(parity);             \
    asm volatile("{\n\t.reg .pred P1;\n\t"                                        \
        "WAIT_LOOP_%=:\n\t"                                                       \
        "mbarrier.try_wait.parity.acquire.cta.shared::cta.b64 P1, [%0], %1, 0x989680;\n\t" \
        "@P1 bra.uni WAIT_DONE_%=;\n\t"                                           \
        "bra.uni WAIT_LOOP_%=;\n\t"                                               \
        "WAIT_DONE_%=:\n\t}" :: "r"(_m), "r"(_p) : "memory");                     \
} while (0)

__device__ __forceinline__ void bulk_g2s(uint32_t dst, const void* src,
                                         uint32_t bytes, uint32_t mbar) {
    asm volatile(
        "cp.async.bulk.shared::cluster.global.mbarrier::complete_tx::bytes "
        "[%0], [%1], %2, [%3];"
        :: "r"(dst), "l"(__cvta_generic_to_global(src)), "r"(bytes), "r"(mbar)
        : "memory");
}

// ldmatrix x4: 4 8x8 b16 matrices; lane supplies one 16B row address
__device__ __forceinline__ void ldsm4(uint32_t* r, uint32_t addr) {
    asm volatile("ldmatrix.sync.aligned.m8n8.x4.shared.b16 {%0,%1,%2,%3}, [%4];"
                 : "=r"(r[0]), "=r"(r[1]), "=r"(r[2]), "=r"(r[3]) : "r"(addr));
}

// m16n8k16 row.col bf16 -> f32, D += A*B (D aliases C)
__device__ __forceinline__ void mma16816(float c[4], const uint32_t a[4],
                                         uint32_t b0, uint32_t b1) {
    asm volatile(
        "mma.sync.aligned.m16n8k16.row.col.f32.bf16.bf16.f32 "
        "{%0,%1,%2,%3}, {%4,%5,%6,%7}, {%8,%9}, {%0,%1,%2,%3};"
        : "+f"(c[0]), "+f"(c[1]), "+f"(c[2]), "+f"(c[3])
        : "r"(a[0]), "r"(a[1]), "r"(a[2]), "r"(a[3]), "r"(b0), "r"(b1));
}

// register-resident ascending insert; v > h[10] is a no-op
__device__ __forceinline__ void bubble_insert(float* h, float v) {
#pragma unroll
    for (int j = 0; j < KSEL; ++j) {
        float lo = fminf(h[j], v);
        v = fmaxf(h[j], v);
        h[j] = lo;
    }
}

// merge my ascending 11-list with lane^mask's; keep 11 smallest, ascending
__device__ __forceinline__ void merge11(float h[KSEL], int mask) {
    float b[KSEL];
#pragma unroll
    for (int j = 0; j < KSEL; ++j) b[j] = __shfl_xor_sync(0xffffffffu, h[j], mask);
    float c[16];
#pragma unroll
    for (int i = 0; i < 5; ++i) c[i] = NEG_INF;
#pragma unroll
    for (int i = 0; i < KSEL; ++i) c[5 + i] = fminf(h[i], b[10 - i]);
#pragma unroll
    for (int d = 8; d >= 1; d >>= 1)
#pragma unroll
        for (int i = 0; i < 16; ++i)
            if ((i & d) == 0) {
                float lo = fminf(c[i], c[i | d]);
                float hi = fmaxf(c[i], c[i | d]);
                c[i] = lo; c[i | d] = hi;
            }
#pragma unroll
    for (int i = 0; i < KSEL; ++i) h[i] = c[5 + i];
}

// ---------------- prep kernels ----------------
__global__ void prep_buf_kernel(const float* __restrict__ buf) {
    int c = blockIdx.x * 256 + threadIdx.x;
    const float4* s = reinterpret_cast<const float4*>(buf) + (size_t)c * 16;
    uint4 pk[8];
    uint32_t* pw = reinterpret_cast<uint32_t*>(pk);
    float n = 0.f;
#pragma unroll
    for (int q = 0; q < 16; ++q) {
        float4 v = s[q];
        n = fmaf(v.x, v.x, n); n = fmaf(v.y, v.y, n);
        n = fmaf(v.z, v.z, n); n = fmaf(v.w, v.w, n);
        __nv_bfloat162 a = __floats2bfloat162_rn(-2.f * v.x, -2.f * v.y);
        __nv_bfloat162 b = __floats2bfloat162_rn(-2.f * v.z, -2.f * v.w);
        pw[2 * q]     = reinterpret_cast<uint32_t&>(a);
        pw[2 * q + 1] = reinterpret_cast<uint32_t&>(b);
    }
    char* blk = reinterpret_cast<char*>(g_bbf) + (size_t)(c >> 8) * TILE_BYTES;
    uint32_t r = (uint32_t)(c & 255);
#pragma unroll
    for (int q = 0; q < 8; ++q)
        *reinterpret_cast<uint4*>(blk + SWZ128(r * 128 + q * 16)) = pk[q];
    g_bnorm[c] = n;
}

__global__ void prep_x_kernel(const float* __restrict__ x) {
    int c = blockIdx.x * 256 + threadIdx.x;
    const float4* s = reinterpret_cast<const float4*>(x) + (size_t)c * 16;
    uint4 pk[8];
    uint32_t* pw = reinterpret_cast<uint32_t*>(pk);
    float n = 0.f;
#pragma unroll
    for (int q = 0; q < 16; ++q) {
        float4 v = s[q];
        n = fmaf(v.x, v.x, n); n = fmaf(v.y, v.y, n);
        n = fmaf(v.z, v.z, n); n = fmaf(v.w, v.w, n);
        __nv_bfloat162 a = __floats2bfloat162_rn(v.x, v.y);
        __nv_bfloat162 b = __floats2bfloat162_rn(v.z, v.w);
        pw[2 * q]     = reinterpret_cast<uint32_t&>(a);
        pw[2 * q + 1] = reinterpret_cast<uint32_t&>(b);
    }
    uint4* dst = reinterpret_cast<uint4*>(g_xbf) + (size_t)c * 8;
#pragma unroll
    for (int i = 0; i < 8; ++i) dst[i] = pk[i];
    g_xnorm[c] = n;
}

// ---------------- static multi-unit fused GEMM + top-k kernel ----------------
extern __shared__ char smem[];

__global__ void __launch_bounds__(THREADS, 1)
pbe_static_kernel() {
    const int tid  = threadIdx.x;
    const int lane = tid & 31;
    const int w    = tid >> 5;           // 0..15
    const int g    = lane >> 2;          // 0..7
    const int tig  = lane & 3;           // 0..3
    const int b    = blockIdx.x;         // 0..147

    const uint32_t sbase = smem_u32(smem);
    const uint32_t mb0   = sbase + SM_MBAR;

    // per-lane ldmatrix offsets (swizzle XOR applied last, no carries)
    const uint32_t l8  = (uint32_t)(lane & 7);
    const uint32_t qof = (uint32_t)((lane >> 3) * 16);
    const uint32_t sw  = l8 << 4;
    const uint32_t lm_off0 = l8 * 128 + (qof ^ sw);          // k bytes 0..63
    const uint32_t lm_off1 = l8 * 128 + ((qof + 64) ^ sw);   // k bytes 64..127

    if (tid == 0) {
        MBARRIER_INIT(mb0 + 0,  1);
        MBARRIER_INIT(mb0 + 8,  1);
        MBARRIER_INIT(mb0 + 16, 1);
    }
    __syncthreads();

    const int nmy     = (NUNITS - b + GRID_MAIN - 1) / GRID_MAIN;  // 6 or 7
    const int ntiles  = nmy * CH_TILES;

    // issue tile tau of MY stream (thread 0 only); 32-bit addressing
    auto issue = [&](int tau) {
        int u = b + (tau >> 2) * GRID_MAIN;
        uint32_t cb = (uint32_t)(((u >> 3) & 15) * CPART
                               + (u & 7) * (CH_TILES * TN)
                               + (tau & 3) * TN);               // candidate idx
        int s = tau % 3;
        uint32_t bar = mb0 + s * 8;
        MBARRIER_EXPECT_TX(bar, TILE_BYTES + BN_BYTES);
        bulk_g2s(sbase + SM_B + s * TILE_BYTES,
                 reinterpret_cast<const char*>(g_bbf) + (size_t)cb * 128,
                 TILE_BYTES, bar);
        bulk_g2s(sbase + SM_BN + s * BN_BYTES, g_bnorm + cb, BN_BYTES, bar);
    };
    if (tid == 0) { issue(0); issue(1); }

    int tau = 0, slot = 0, par = 0;      // continuous tile stream state

    for (int i = 0; i < nmy; ++i) {
        const int u = b + i * GRID_MAIN;
        const int row_base = (u >> 7) * ROWS_CTA + w * 16;
        const int li = u & 127;          // part*NCHUNK + chunk

        // ---- A fragments for this unit's rows ----
        uint32_t afr[4][4];
        {
            const uint32_t* x0 = reinterpret_cast<const uint32_t*>(
                g_xbf + (size_t)(row_base + g) * DIM);
            const uint32_t* x1 = reinterpret_cast<const uint32_t*>(
                g_xbf + (size_t)(row_base + g + 8) * DIM);
#pragma unroll
            for (int kc = 0; kc < 4; ++kc) {
                afr[kc][0] = x0[kc * 8 + tig];
                afr[kc][1] = x1[kc * 8 + tig];
                afr[kc][2] = x0[kc * 8 + tig + 4];
                afr[kc][3] = x1[kc * 8 + tig + 4];
            }
        }

        float h0[KSEL], h1[KSEL];
#pragma unroll
        for (int j = 0; j < KSEL; ++j) { h0[j] = POS_INF; h1[j] = POS_INF; }

        for (int t = 0; t < CH_TILES; ++t) {
            __syncthreads();             // all warps done with tile tau-1 data
            if (tid == 0 && tau + 2 < ntiles) issue(tau + 2);
            MBARRIER_WAIT_PARITY(mb0 + slot * 8, par);

            const uint32_t tb0 = sbase + SM_B + slot * TILE_BYTES + lm_off0;
            const uint32_t tb1 = sbase + SM_B + slot * TILE_BYTES + lm_off1;
            const float*   bns = reinterpret_cast<const float*>(
                                     smem + SM_BN + slot * BN_BYTES) + tig * 2;

            uint32_t fA[2][8], fB[2][8];
            auto load_pair = [&](int p, uint32_t f[2][8]) {
                const uint32_t po = (uint32_t)(p * 2048);
                ldsm4(&f[0][0], tb0 + po);               // nb=2p,   k 0..31
                ldsm4(&f[0][4], tb1 + po);               // nb=2p,   k 32..63
                ldsm4(&f[1][0], tb0 + po + 1024);        // nb=2p+1, k 0..31
                ldsm4(&f[1][4], tb1 + po + 1024);        // nb=2p+1, k 32..63
            };
            load_pair(0, fA);

#pragma unroll
            for (int p = 0; p < 16; ++p) {
                uint32_t (*fc)[8] = (p & 1) ? fB : fA;
                uint32_t (*fn)[8] = (p & 1) ? fA : fB;
                if (p < 15) load_pair(p + 1, fn);

                float acc[2][4];
#pragma unroll
                for (int q = 0; q < 2; ++q) {
                    const float2 bnv = *reinterpret_cast<const float2*>(
                        &bns[(p * 2 + q) * 8]);
                    acc[q][0] = bnv.x; acc[q][1] = bnv.y;
                    acc[q][2] = bnv.x; acc[q][3] = bnv.y;
                }
#pragma unroll
                for (int kc = 0; kc < 4; ++kc) {
                    mma16816(acc[0], afr[kc], fc[0][kc * 2], fc[0][kc * 2 + 1]);
                    mma16816(acc[1], afr[kc], fc[1][kc * 2], fc[1][kc * 2 + 1]);
                }
                // acc IS the distance (bn - 2*dot); |x|^2 deferred
#pragma unroll
                for (int q = 0; q < 2; ++q) {
                    if (fminf(acc[q][0], acc[q][1]) < h0[KSEL - 1]) {
                        if (acc[q][0] < h0[KSEL - 1]) bubble_insert(h0, acc[q][0]);
                        if (acc[q][1] < h0[KSEL - 1]) bubble_insert(h0, acc[q][1]);
                    }
                    if (fminf(acc[q][2], acc[q][3]) < h1[KSEL - 1]) {
                        if (acc[q][2] < h1[KSEL - 1]) bubble_insert(h1, acc[q][2]);
                        if (acc[q][3] < h1[KSEL - 1]) bubble_insert(h1, acc[q][3]);
                    }
                }
            }

            ++tau;
            if (++slot == 3) { slot = 0; par ^= 1; }
        }

        // ---- merge across the 4 tig lanes; tig 0 writes 1 list per row ----
        merge11(h0, 1); merge11(h0, 2);
        merge11(h1, 1); merge11(h1, 2);
        if (tig == 0) {
            float* p0 = &g_partial[((size_t)(row_base + g)     * NLISTS + li) * KSEL];
            float* p1 = &g_partial[((size_t)(row_base + g + 8) * NLISTS + li) * KSEL];
#pragma unroll
            for (int j = 0; j < KSEL; ++j) { p0[j] = h0[j]; p1[j] = h1[j]; }
        }
    }
}

// ---------------- final merge kernel: 128 threads per row ----------------
__global__ void final_kernel(float* __restrict__ out) {
    __shared__ float wl[4][KSEL];
    const int tid  = threadIdx.x;        // 0..127 <-> list index
    const int lane = tid & 31;
    const int w    = tid >> 5;
    const int row  = blockIdx.x;

    float h[KSEL];
    const float* p = &g_partial[((size_t)row * NLISTS + tid) * KSEL];
#pragma unroll
    for (int j = 0; j < KSEL; ++j) h[j] = p[j];

    merge11(h, 1); merge11(h, 2); merge11(h, 4); merge11(h, 8); merge11(h, 16);
    if (lane == 0) {
#pragma unroll
        for (int j = 0; j < KSEL; ++j) wl[w][j] = h[j];
    }
    __syncthreads();
    if (tid == 0) {
#pragma unroll
        for (int ww = 1; ww < 4; ++ww)
            for (int j = 0; j < KSEL; ++j) {
                float v = wl[ww][j];
                if (v < h[KSEL - 1]) bubble_insert(h, v);
                else break;              // lists are sorted ascending
            }
        float xn = g_xnorm[row];
        float s = 0.f;
#pragma unroll
        for (int j = 1; j < KSEL; ++j)          // drop self-match (h[0])
            s += sqrtf(fmaxf(xn + h[j], 0.f));
        out[row] = log1pf(s * (1.f / (KSEL - 1)));
    }
}

// ---------------- launch ----------------
extern "C" void kernel_launch(void* const* d_in, const int* in_sizes, int n_in,
                              void* d_out, int out_size) {
    const float* a = (const float*)d_in[0];
    const float* b = (const float*)d_in[1];
    const float* x = a;
    const float* buf = b;
    if (in_sizes[0] > in_sizes[1]) { x = b; buf = a; }

    cudaFuncSetAttribute(pbe_static_kernel,
                         cudaFuncAttributeMaxDynamicSharedMemorySize, SMEM_TOTAL);

    prep_buf_kernel<<<M_CANDS / 256, 256>>>(buf);
    prep_x_kernel<<<N_ROWS / 256, 256>>>(x);

    pbe_static_kernel<<<GRID_MAIN, THREADS, SMEM_TOTAL>>>();

    final_kernel<<<N_ROWS, 128>>>((float*)d_out);
}

// round 13
// speedup vs baseline: 1.9926x; 1.5570x over previous
#include <cuda_runtime.h>
#include <cuda_bf16.h>
#include <cstdint>

// ---------------- problem constants ----------------
#define M_CANDS 131072
#define N_ROWS  2048
#define DIM     64
#define KSEL    11                 // k+1 smallest; smallest (self) dropped later

// ---------------- tiling / ragged static decomposition ----------------
#define ROWS_CTA 256                     // x rows per CTA (16 warps x 16 rows)
#define ROWTILES (N_ROWS / ROWS_CTA)     // 8
#define TN       256                     // candidates per smem tile
#define NTILES   (M_CANDS / TN)          // 512 tile-columns per rowtile
#define THREADS  512
#define GRID_MAIN 148                    // rowtiles 0-3: 19 CTAs, 4-7: 18 CTAs
#define MAXL     19                      // max lists per row
#define TILE_BYTES (TN * 128)            // 32768
#define BN_BYTES   (TN * 4)              // 1024

// ---------------- smem layout (bytes) ----------------
#define SM_MBAR  0                       // 3 mbarriers
#define SM_B     1024
#define SM_BN    (SM_B + 3 * TILE_BYTES)          // 99328
#define SMEM_TOTAL (SM_BN + 3 * BN_BYTES)         // 102400

#define POS_INF __int_as_float(0x7f800000)
#define NEG_INF __int_as_float(0xff800000)

// ---------------- device globals (allocation-free scratch) ----------------
__device__ __align__(128) __nv_bfloat16 g_bbf[(size_t)M_CANDS * DIM]; // -2*buf, bf16, tile-swizzled
__device__ __align__(16)  __nv_bfloat16 g_xbf[(size_t)N_ROWS * DIM];
__device__ __align__(16)  float g_bnorm[M_CANDS];
__device__ __align__(16)  float g_xnorm[N_ROWS];
__device__ __align__(16)  float g_partial[(size_t)N_ROWS * MAXL * KSEL];

// ---------------- helpers ----------------
__device__ __forceinline__ uint32_t smem_u32(const void* p) {
    return (uint32_t)__cvta_generic_to_shared(p);
}
#define SWZ128(off) ((off) ^ (((off) >> 3) & 0x70))

#define MBARRIER_INIT(mbar, cnt) \
    asm volatile("mbarrier.init.shared.b64 [%0], %1;" \
                 :: "r"((uint32_t)(mbar)), "r"((uint32_t)(cnt)) : "memory")
#define MBARRIER_EXPECT_TX(mbar, bytes) \
    asm volatile("mbarrier.arrive.expect_tx.shared.b64 _, [%0], %1;" \
                 :: "r"((uint32_t)(mbar)), "r"((uint32_t)(bytes)) : "memory")
#define MBARRIER_WAIT_PARITY(mbar, parity) do {                                   \
    uint32_t _m = (uint32_t)(mbar); uint32_t _p = (uint32_t)(parity);             \
    asm volatile("{\n\t.reg .pred P1;\n\t"                                        \
        "WAIT_LOOP_%=:\n\t"                                                       \
        "mbarrier.try_wait.parity.acquire.cta.shared::cta.b64 P1, [%0], %1, 0x989680;\n\t" \
        "@P1 bra.uni WAIT_DONE_%=;\n\t"                                           \
        "bra.uni WAIT_LOOP_%=;\n\t"                                               \
        "WAIT_DONE_%=:\n\t}" :: "r"(_m), "r"(_p) : "memory");                     \
} while (0)

__device__ __forceinline__ void bulk_g2s(uint32_t dst, const void* src,
                                         uint32_t bytes, uint32_t mbar) {
    asm volatile(
        "cp.async.bulk.shared::cluster.global.mbarrier::complete_tx::bytes "
        "[%0], [%1], %2, [%3];"
        :: "r"(dst), "l"(__cvta_generic_to_global(src)), "r"(bytes), "r"(mbar)
        : "memory");
}

// ldmatrix x4: 4 8x8 b16 matrices; lane supplies one 16B row address
__device__ __forceinline__ void ldsm4(uint32_t* r, uint32_t addr) {
    asm volatile("ldmatrix.sync.aligned.m8n8.x4.shared.b16 {%0,%1,%2,%3}, [%4];"
                 : "=r"(r[0]), "=r"(r[1]), "=r"(r[2]), "=r"(r[3]) : "r"(addr));
}

// m16n8k16 row.col bf16 -> f32, D += A*B (D aliases C)
__device__ __forceinline__ void mma16816(float c[4], const uint32_t a[4],
                                         uint32_t b0, uint32_t b1) {
    asm volatile(
        "mma.sync.aligned.m16n8k16.row.col.f32.bf16.bf16.f32 "
        "{%0,%1,%2,%3}, {%4,%5,%6,%7}, {%8,%9}, {%0,%1,%2,%3};"
        : "+f"(c[0]), "+f"(c[1]), "+f"(c[2]), "+f"(c[3])
        : "r"(a[0]), "r"(a[1]), "r"(a[2]), "r"(a[3]), "r"(b0), "r"(b1));
}

// register-resident ascending insert; v > h[10] is a no-op
__device__ __forceinline__ void bubble_insert(float* h, float v) {
#pragma unroll
    for (int j = 0; j < KSEL; ++j) {
        float lo = fminf(h[j], v);
        v = fmaxf(h[j], v);
        h[j] = lo;
    }
}

// merge my ascending 11-list with lane^mask's; keep 11 smallest, ascending
__device__ __forceinline__ void merge11(float h[KSEL], int mask) {
    float b[KSEL];
#pragma unroll
    for (int j = 0; j < KSEL; ++j) b[j] = __shfl_xor_sync(0xffffffffu, h[j], mask);
    float c[16];
#pragma unroll
    for (int i = 0; i < 5; ++i) c[i] = NEG_INF;
#pragma unroll
    for (int i = 0; i < KSEL; ++i) c[5 + i] = fminf(h[i], b[10 - i]);
#pragma unroll
    for (int d = 8; d >= 1; d >>= 1)
#pragma unroll
        for (int i = 0; i < 16; ++i)
            if ((i & d) == 0) {
                float lo = fminf(c[i], c[i | d]);
                float hi = fmaxf(c[i], c[i | d]);
                c[i] = lo; c[i | d] = hi;
            }
#pragma unroll
    for (int i = 0; i < KSEL; ++i) h[i] = c[5 + i];
}

// ---------------- prep kernels ----------------
__global__ void prep_buf_kernel(const float* __restrict__ buf) {
    int c = blockIdx.x * 256 + threadIdx.x;
    const float4* s = reinterpret_cast<const float4*>(buf) + (size_t)c * 16;
    uint4 pk[8];
    uint32_t* pw = reinterpret_cast<uint32_t*>(pk);
    float n = 0.f;
#pragma unroll
    for (int q = 0; q < 16; ++q) {
        float4 v = s[q];
        n = fmaf(v.x, v.x, n); n = fmaf(v.y, v.y, n);
        n = fmaf(v.z, v.z, n); n = fmaf(v.w, v.w, n);
        __nv_bfloat162 a = __floats2bfloat162_rn(-2.f * v.x, -2.f * v.y);
        __nv_bfloat162 b = __floats2bfloat162_rn(-2.f * v.z, -2.f * v.w);
        pw[2 * q]     = reinterpret_cast<uint32_t&>(a);
        pw[2 * q + 1] = reinterpret_cast<uint32_t&>(b);
    }
    char* blk = reinterpret_cast<char*>(g_bbf) + (size_t)(c >> 8) * TILE_BYTES;
    uint32_t r = (uint32_t)(c & 255);
#pragma unroll
    for (int q = 0; q < 8; ++q)
        *reinterpret_cast<uint4*>(blk + SWZ128(r * 128 + q * 16)) = pk[q];
    g_bnorm[c] = n;
}

__global__ void prep_x_kernel(const float* __restrict__ x) {
    int c = blockIdx.x * 256 + threadIdx.x;
    const float4* s = reinterpret_cast<const float4*>(x) + (size_t)c * 16;
    uint4 pk[8];
    uint32_t* pw = reinterpret_cast<uint32_t*>(pk);
    float n = 0.f;
#pragma unroll
    for (int q = 0; q < 16; ++q) {
        float4 v = s[q];
        n = fmaf(v.x, v.x, n); n = fmaf(v.y, v.y, n);
        n = fmaf(v.z, v.z, n); n = fmaf(v.w, v.w, n);
        __nv_bfloat162 a = __floats2bfloat162_rn(v.x, v.y);
        __nv_bfloat162 b = __floats2bfloat162_rn(v.z, v.w);
        pw[2 * q]     = reinterpret_cast<uint32_t&>(a);
        pw[2 * q + 1] = reinterpret_cast<uint32_t&>(b);
    }
    uint4* dst = reinterpret_cast<uint4*>(g_xbf) + (size_t)c * 8;
#pragma unroll
    for (int i = 0; i < 8; ++i) dst[i] = pk[i];
    g_xnorm[c] = n;
}

// ---------------- main fused GEMM + top-k kernel (single unit per CTA) ----
extern __shared__ char smem[];

__global__ void __launch_bounds__(THREADS, 1)
pbe_mma_kernel() {
    const int tid  = threadIdx.x;
    const int lane = tid & 31;
    const int w    = tid >> 5;           // 0..15
    const int g    = lane >> 2;          // 0..7
    const int tig  = lane & 3;           // 0..3

    // ---- ragged static assignment: (rowtile, contiguous tile range) ----
    int rt, c, nc;
    {
        const int b = blockIdx.x;        // 0..147
        if (b < 76) { rt = b / 19; c = b - rt * 19; nc = 19; }
        else { int b2 = b - 76; rt = 4 + b2 / 18; c = b2 - (rt - 4) * 18; nc = 18; }
    }
    const int t0 = (NTILES * c) / nc;
    const int nt = (NTILES * (c + 1)) / nc - t0;   // 26..29 tiles
    const int row_base = rt * ROWS_CTA + w * 16;

    const uint32_t sbase = smem_u32(smem);
    const uint32_t mb0   = sbase + SM_MBAR;

    // ---- A fragments: 1 m-block (16 rows) per warp, persistent ----
    uint32_t afr[4][4];
    {
        const uint32_t* x0 = reinterpret_cast<const uint32_t*>(
            g_xbf + (size_t)(row_base + g) * DIM);
        const uint32_t* x1 = reinterpret_cast<const uint32_t*>(
            g_xbf + (size_t)(row_base + g + 8) * DIM);
#pragma unroll
        for (int kc = 0; kc < 4; ++kc) {
            afr[kc][0] = x0[kc * 8 + tig];
            afr[kc][1] = x1[kc * 8 + tig];
            afr[kc][2] = x0[kc * 8 + tig + 4];
            afr[kc][3] = x1[kc * 8 + tig + 4];
        }
    }

    // ---- per-lane ldmatrix offsets (swizzle XOR applied last, no carries) ----
    const uint32_t l8  = (uint32_t)(lane & 7);
    const uint32_t qof = (uint32_t)((lane >> 3) * 16);
    const uint32_t sw  = l8 << 4;
    const uint32_t lm_off0 = l8 * 128 + (qof ^ sw);          // k bytes 0..63
    const uint32_t lm_off1 = l8 * 128 + ((qof + 64) ^ sw);   // k bytes 64..127

    // ---- mbarriers + prologue staging ----
    if (tid == 0) {
        MBARRIER_INIT(mb0 + 0,  1);
        MBARRIER_INIT(mb0 + 8,  1);
        MBARRIER_INIT(mb0 + 16, 1);
    }
    __syncthreads();

    auto issue = [&](int t) {            // thread 0 only
        int s = t % 3;
        uint32_t bar = mb0 + s * 8;
        uint32_t cb = (uint32_t)(t0 + t) * TN;   // candidate index
        MBARRIER_EXPECT_TX(bar, TILE_BYTES + BN_BYTES);
        bulk_g2s(sbase + SM_B + s * TILE_BYTES,
                 reinterpret_cast<const char*>(g_bbf) + (size_t)cb * 128,
                 TILE_BYTES, bar);
        bulk_g2s(sbase + SM_BN + s * BN_BYTES, g_bnorm + cb, BN_BYTES, bar);
    };
    if (tid == 0) { issue(0); issue(1); }

    // ---- top-11 lists for this thread's 2 rows ----
    float h0[KSEL], h1[KSEL];
#pragma unroll
    for (int j = 0; j < KSEL; ++j) { h0[j] = POS_INF; h1[j] = POS_INF; }

    uint32_t ph[3] = {0, 0, 0};

    for (int t = 0; t < nt; ++t) {
        const int slot = t % 3;
        __syncthreads();                 // all warps finished compute(t-1)
        if (t + 2 < nt && tid == 0) issue(t + 2);
        MBARRIER_WAIT_PARITY(mb0 + slot * 8, ph[slot]);
        ph[slot] ^= 1;

        const uint32_t tb0 = sbase + SM_B + slot * TILE_BYTES + lm_off0;
        const uint32_t tb1 = sbase + SM_B + slot * TILE_BYTES + lm_off1;
        const float*   bns = reinterpret_cast<const float*>(
                                 smem + SM_BN + slot * BN_BYTES) + tig * 2;

        uint32_t fA[2][8], fB[2][8];
        auto load_pair = [&](int p, uint32_t f[2][8]) {
            const uint32_t po = (uint32_t)(p * 2048);
            ldsm4(&f[0][0], tb0 + po);               // nb=2p,   k 0..31
            ldsm4(&f[0][4], tb1 + po);               // nb=2p,   k 32..63
            ldsm4(&f[1][0], tb0 + po + 1024);        // nb=2p+1, k 0..31
            ldsm4(&f[1][4], tb1 + po + 1024);        // nb=2p+1, k 32..63
        };
        load_pair(0, fA);

#pragma unroll
        for (int p = 0; p < 16; ++p) {
            uint32_t (*fc)[8] = (p & 1) ? fB : fA;
            uint32_t (*fn)[8] = (p & 1) ? fA : fB;
            if (p < 15) load_pair(p + 1, fn);

            float acc[2][4];
#pragma unroll
            for (int q = 0; q < 2; ++q) {
                const float2 bnv = *reinterpret_cast<const float2*>(
                    &bns[(p * 2 + q) * 8]);
                acc[q][0] = bnv.x; acc[q][1] = bnv.y;
                acc[q][2] = bnv.x; acc[q][3] = bnv.y;
            }
#pragma unroll
            for (int kc = 0; kc < 4; ++kc) {
                mma16816(acc[0], afr[kc], fc[0][kc * 2], fc[0][kc * 2 + 1]);
                mma16816(acc[1], afr[kc], fc[1][kc * 2], fc[1][kc * 2 + 1]);
            }
            // acc IS the distance (bn - 2*dot); |x|^2 deferred
#pragma unroll
            for (int q = 0; q < 2; ++q) {
                if (fminf(acc[q][0], acc[q][1]) < h0[KSEL - 1]) {
                    if (acc[q][0] < h0[KSEL - 1]) bubble_insert(h0, acc[q][0]);
                    if (acc[q][1] < h0[KSEL - 1]) bubble_insert(h0, acc[q][1]);
                }
                if (fminf(acc[q][2], acc[q][3]) < h1[KSEL - 1]) {
                    if (acc[q][2] < h1[KSEL - 1]) bubble_insert(h1, acc[q][2]);
                    if (acc[q][3] < h1[KSEL - 1]) bubble_insert(h1, acc[q][3]);
                }
            }
        }
    }

    // ---- merge across the 4 tig lanes; tig 0 writes 1 list per row ----
    merge11(h0, 1); merge11(h0, 2);
    merge11(h1, 1); merge11(h1, 2);
    if (tig == 0) {
        float* p0 = &g_partial[((size_t)(row_base + g)     * MAXL + c) * KSEL];
        float* p1 = &g_partial[((size_t)(row_base + g + 8) * MAXL + c) * KSEL];
#pragma unroll
        for (int j = 0; j < KSEL; ++j) { p0[j] = h0[j]; p1[j] = h1[j]; }
    }
}

// ---------------- final merge kernel: one warp per row ----------------
__global__ void final_kernel(float* __restrict__ out) {
    const int row  = blockIdx.x * 8 + (threadIdx.x >> 5);
    const int lane = threadIdx.x & 31;
    const int nc   = (row < 4 * ROWS_CTA) ? 19 : 18;   // lists for this rowtile

    float h[KSEL];
    if (lane < nc) {
        const float* p = &g_partial[((size_t)row * MAXL + lane) * KSEL];
#pragma unroll
        for (int j = 0; j < KSEL; ++j) h[j] = p[j];
    } else {
#pragma unroll
        for (int j = 0; j < KSEL; ++j) h[j] = POS_INF;
    }
    merge11(h, 1); merge11(h, 2); merge11(h, 4); merge11(h, 8); merge11(h, 16);

    if (lane == 0) {
        float xn = g_xnorm[row];
        float s = 0.f;
#pragma unroll
        for (int j = 1; j < KSEL; ++j)          // drop self-match (h[0])
            s += sqrtf(fmaxf(xn + h[j], 0.f));
        out[row] = log1pf(s * (1.f / (KSEL - 1)));
    }
}

// ---------------- launch ----------------
extern "C" void kernel_launch(void* const* d_in, const int* in_sizes, int n_in,
                              void* d_out, int out_size) {
    const float* a = (const float*)d_in[0];
    const float* b = (const float*)d_in[1];
    const float* x = a;
    const float* buf = b;
    if (in_sizes[0] > in_sizes[1]) { x = b; buf = a; }

    cudaFuncSetAttribute(pbe_mma_kernel,
                         cudaFuncAttributeMaxDynamicSharedMemorySize, SMEM_TOTAL);

    prep_buf_kernel<<<M_CANDS / 256, 256>>>(buf);
    prep_x_kernel<<<N_ROWS / 256, 256>>>(x);

    pbe_mma_kernel<<<GRID_MAIN, THREADS, SMEM_TOTAL>>>();

    final_kernel<<<N_ROWS / 8, 256>>>((float*)d_out);
}